// round 5
// baseline (speedup 1.0000x reference)
#include <cuda_runtime.h>
#include <cstdint>

#define B_   64
#define TT   512
#define VV   32
#define LF   160          // fwd vector steps  [0,160)
#define LB   160          // bwd vector steps  [352,512)
#define TOFF 160          // chunk region start
#define NCH  6            // chunks per batch (6*32 = 192 middle steps)
#define LL   32           // steps per chunk
#define NSTF 8            // fwd pipeline stages
#define NSTB 6            // bwd pipeline stages
#define NSTG 4            // chunk pipeline stages
#define NTHR 128
#define F_LOG2E 1.4426950408889634f
#define F_LN2   0.6931471805599453f

typedef unsigned long long ull;

// ---- global scratch ----
__device__ float g_P[B_*NCH*VV*VV];
__device__ float g_Ac[B_*NCH];
__device__ float g_numc[B_*NCH];
__device__ float g_alpha[B_*VV];
__device__ float g_beta[B_*VV];
__device__ float g_Af[B_], g_Ab[B_];
__device__ float g_numf[B_], g_numb[B_];

__device__ __forceinline__ float ex2f_(float x){ float y; asm("ex2.approx.ftz.f32 %0, %1;" : "=f"(y) : "f"(x)); return y; }
__device__ __forceinline__ float lg2f_(float x){ float y; asm("lg2.approx.ftz.f32 %0, %1;" : "=f"(y) : "f"(x)); return y; }
__device__ __forceinline__ ull add2_(ull a, ull b){ ull r; asm("add.rn.f32x2 %0, %1, %2;" : "=l"(r) : "l"(a), "l"(b)); return r; }
__device__ __forceinline__ ull mul2_(ull a, ull b){ ull r; asm("mul.rn.f32x2 %0, %1, %2;" : "=l"(r) : "l"(a), "l"(b)); return r; }
__device__ __forceinline__ ull fma2_(ull a, ull b, ull c){ ull r; asm("fma.rn.f32x2 %0, %1, %2, %3;" : "=l"(r) : "l"(a), "l"(b), "l"(c)); return r; }
__device__ __forceinline__ ull pack2_(float lo, float hi){ ull r; asm("mov.b64 %0, {%1, %2};" : "=l"(r) : "f"(lo), "f"(hi)); return r; }
__device__ __forceinline__ void unpack2_(ull v, float& lo, float& hi){ asm("mov.b64 {%0, %1}, %2;" : "=f"(lo), "=f"(hi) : "l"(v)); }
__device__ __forceinline__ void cpasync16(float* s, const float* g){
  uint32_t sa = (uint32_t)__cvta_generic_to_shared(s);
  asm volatile("cp.async.cg.shared.global [%0], [%1], 16;" :: "r"(sa), "l"(g));
}
__device__ __forceinline__ int tgt_is64(const int* t32){
  int is64 = 1;
  #pragma unroll
  for (int k = 1; k < 64; k += 2) if (t32[k] != 0) is64 = 0;
  return is64;
}
__device__ __forceinline__ int ld_tgt(const void* traw, int is64, long long idx){
  return is64 ? (int)((const long long*)traw)[idx] : ((const int*)traw)[idx];
}

__global__ void knop(){}

// ===================== fused heterogeneous kernel =====================
// blockIdx: [0,64) fwd | [64,128) bwd | [128,512) chunk
__global__ __launch_bounds__(NTHR)
void crf_fused(const float* __restrict__ scores,
               const void*  __restrict__ targets_raw,
               const float* __restrict__ w_tx,
               const float* __restrict__ w_init,
               const float* __restrict__ w_final,
               const float* __restrict__ w_dur)
{
  __shared__ __align__(16) char pool[39456];
  const int bid = blockIdx.x;
  const int tid = threadIdx.x;
  const int j   = tid & 31;
  const int w   = tid >> 5;
  const int is64 = tgt_is64((const int*)targets_raw);

  if (bid < 64) {
    // ======================= FORWARD vector scan: t in [0, LF) =======================
    const int b = bid;
    float* tile = (float*)(pool);                 // NSTF * 1024 floats
    float* part = (float*)(pool + 32768);         // 2*4*32
    float* craw = (float*)(pool + 33792);         // 1024
    int*   tg   = (int*)  (pool + 37888);         // LF+1
    const float* sb = scores + (size_t)b * TT * VV * VV;
    const int i0 = w * 8;

    for (int k = tid; k < VV*VV; k += NTHR) craw[k] = w_tx[k] + w_dur[k];
    for (int k = tid; k < LF+1; k += NTHR) tg[k] = ld_tgt(targets_raw, is64, (long long)b*(TT+1) + k);
    part[0*128 + w*32 + j] = (w == 0) ? ex2f_(w_init[j] * F_LOG2E) : 0.f;

    for (int p = 0; p < NSTF-1; ++p){
      cpasync16(&tile[p*1024 + tid*8],     sb + p*VV*VV + tid*8);
      cpasync16(&tile[p*1024 + tid*8 + 4], sb + p*VV*VV + tid*8 + 4);
      asm volatile("cp.async.commit_group;");
    }
    __syncthreads();

    float c2[8];
    #pragma unroll
    for (int d = 0; d < 8; ++d) c2[d] = craw[(i0+d)*VV + j] * F_LOG2E;

    asm volatile("cp.async.wait_group %0;" :: "n"(NSTF-2));
    __syncwarp();
    float e_[8];
    #pragma unroll
    for (int d = 0; d < 8; ++d)
      e_[d] = ex2f_(fmaf(tile[0*1024 + (i0+d)*VV + j], F_LOG2E, c2[d]));

    int A = 0; float num = 0.f;
    int s_cur = 0, s_nxt = 1, s_wr = NSTF-1;

    for (int t = 0; t < LF; ++t){
      asm volatile("cp.async.wait_group %0;" :: "n"(NSTF-3));   // tile t+1 in
      __syncwarp();
      const float* tn = &tile[s_nxt*1024];
      float en[8];
      #pragma unroll
      for (int d = 0; d < 8; ++d)
        en[d] = ex2f_(fmaf(tn[(i0+d)*VV + j], F_LOG2E, c2[d]));

      __syncthreads();

      const int pb = t & 1;
      const float* pp = &part[pb*128];
      ulonglong2 p0 = *(const ulonglong2*)(pp + 0*VV + i0);
      ulonglong2 p1 = *(const ulonglong2*)(pp + 1*VV + i0);
      ulonglong2 p2 = *(const ulonglong2*)(pp + 2*VV + i0);
      ulonglong2 p3 = *(const ulonglong2*)(pp + 3*VV + i0);
      ulonglong2 q0 = *(const ulonglong2*)(pp + 0*VV + i0 + 4);
      ulonglong2 q1 = *(const ulonglong2*)(pp + 1*VV + i0 + 4);
      ulonglong2 q2 = *(const ulonglong2*)(pp + 2*VV + i0 + 4);
      ulonglong2 q3 = *(const ulonglong2*)(pp + 3*VV + i0 + 4);

      ull uA = add2_(add2_(p0.x, p1.x), add2_(p2.x, p3.x));
      ull uB = add2_(add2_(p0.y, p1.y), add2_(p2.y, p3.y));
      ull uC = add2_(add2_(q0.x, q1.x), add2_(q2.x, q3.x));
      ull uD = add2_(add2_(q0.y, q1.y), add2_(q2.y, q3.y));

      float ut0 = (pp[0] + pp[VV]) + (pp[2*VV] + pp[3*VV]);
      int esh = ((__float_as_int(ut0) >> 23) & 255) - 127;
      esh = esh < -126 ? -126 : (esh > 126 ? 126 : esh);
      float sc = __int_as_float((127 - esh) << 23);
      A += esh;

      ull e01 = pack2_(e_[0], e_[1]);
      ull e23 = pack2_(e_[2], e_[3]);
      ull e45 = pack2_(e_[4], e_[5]);
      ull e67 = pack2_(e_[6], e_[7]);
      ull m0 = fma2_(e23, uB, mul2_(e01, uA));
      ull m1 = fma2_(e67, uD, mul2_(e45, uC));
      ull m  = add2_(m0, m1);
      float lo, hi; unpack2_(m, lo, hi);
      part[(pb^1)*128 + w*32 + j] = (lo + hi) * sc;

      if (tid == 32){
        int idx = tg[t]*VV + tg[t+1];
        num += tile[s_cur*1024 + idx] + craw[idx];
      }

      { int tl = t + NSTF - 1;
        if (tl < LF){
          float* d = &tile[s_wr*1024];
          const float* g = sb + (size_t)tl*VV*VV;
          cpasync16(d + tid*8,     g + tid*8);
          cpasync16(d + tid*8 + 4, g + tid*8 + 4);
        }
        asm volatile("cp.async.commit_group;");
      }

      #pragma unroll
      for (int d = 0; d < 8; ++d) e_[d] = en[d];
      s_cur = s_nxt;
      s_nxt = (s_nxt+1 == NSTF) ? 0 : s_nxt+1;
      s_wr  = (s_wr +1 == NSTF) ? 0 : s_wr +1;
    }
    __syncthreads();
    if (w == 0){
      // LF even -> final partials in buffer 0
      g_alpha[b*VV + j] = part[0*128 + 0*32 + j] + part[0*128 + 1*32 + j]
                        + part[0*128 + 2*32 + j] + part[0*128 + 3*32 + j];
      if (j == 0) g_Af[b] = (float)A;
    }
    if (tid == 32) g_numf[b] = num + w_init[tg[0]];

  } else if (bid < 128) {
    // ======================= BACKWARD vector scan: t in [352, 512) =======================
    // beta_t = E_t * beta_{t+1};  process t = 511 down to 352.
    const int b = bid - 64;
    float* tile = (float*)(pool);                 // NSTB * 1024
    float* Ecm  = (float*)(pool + 24576);         // 2 * 1024, column-major [j][i]
    float* part = (float*)(pool + 32768);         // 2*4*32 : part[pb][w][i]
    int*   tg   = (int*)  (pool + 33792);         // LB+1 (window 352..512)
    const float* sb = scores + (size_t)b * TT * VV * VV;   // indexed by absolute t

    for (int k = tid; k < LB+1; k += NTHR)
      tg[k] = ld_tgt(targets_raw, is64, (long long)b*(TT+1) + (TT - LB) + k);
    part[0*128 + w*32 + j] = (w == 0) ? ex2f_(w_final[j] * F_LOG2E) : 0.f;

    // my own 8 cells (row r = tid/4, cols c0..c0+7)
    const int r_ = tid >> 2, c0 = (tid & 3) * 8;
    float c2own[8];
    #pragma unroll
    for (int k = 0; k < 8; ++k)
      c2own[k] = (w_tx[r_*VV + c0 + k] + w_dur[r_*VV + c0 + k]) * F_LOG2E;

    // prologue: tiles for k=0..NSTB-2  (t = 511-k)
    for (int p = 0; p < NSTB-1; ++p){
      const float* g = sb + (size_t)(TT-1-p)*VV*VV;
      cpasync16(&tile[p*1024 + tid*8],     g + tid*8);
      cpasync16(&tile[p*1024 + tid*8 + 4], g + tid*8 + 4);
      asm volatile("cp.async.commit_group;");
    }
    __syncthreads();

    int A = 0; float num = 0.f;

    for (int k = 0; k < LB; ++k){
      const int t    = TT - 1 - k;      // absolute time step
      const int slot = k % NSTB;
      const int eb   = k & 1;
      asm volatile("cp.async.wait_group %0;" :: "n"(NSTB-2));

      // exp own cells -> column-major E (pre-barrier, own data)
      {
        const float* tp = &tile[slot*1024 + tid*8];
        float* ec = &Ecm[eb*1024];
        #pragma unroll
        for (int m = 0; m < 8; ++m)
          ec[(c0+m)*VV + r_] = ex2f_(fmaf(tp[m], F_LOG2E, c2own[m]));
      }
      __syncthreads();   // Ecm[eb] ready; part[pb] (written pre-prev-barrier) visible

      { int kl = k + NSTB - 1;
        if (kl < LB){
          float* d = &tile[(kl % NSTB)*1024];
          const float* g = sb + (size_t)(TT-1-kl)*VV*VV;
          cpasync16(d + tid*8,     g + tid*8);
          cpasync16(d + tid*8 + 4, g + tid*8 + 4);
        }
        asm volatile("cp.async.commit_group;");
      }

      if (tid == 0){
        int idx = tg[t - (TT-LB)]*VV + tg[t - (TT-LB) + 1];
        num += tile[slot*1024 + idx] + (w_tx[idx] + w_dur[idx]);
      }

      // combine partials -> beta for my warp's 8 columns (broadcast float4 loads)
      const int pb = k & 1;
      const float* pp = &part[pb*128];
      float4 a0 = *(const float4*)(pp + 0*VV + 8*w);
      float4 a1 = *(const float4*)(pp + 1*VV + 8*w);
      float4 a2 = *(const float4*)(pp + 2*VV + 8*w);
      float4 a3 = *(const float4*)(pp + 3*VV + 8*w);
      float4 b0 = *(const float4*)(pp + 0*VV + 8*w + 4);
      float4 b1 = *(const float4*)(pp + 1*VV + 8*w + 4);
      float4 b2 = *(const float4*)(pp + 2*VV + 8*w + 4);
      float4 b3 = *(const float4*)(pp + 3*VV + 8*w + 4);

      float ut0 = (pp[0] + pp[VV]) + (pp[2*VV] + pp[3*VV]);   // beta[0] (uniform)
      int esh = ((__float_as_int(ut0) >> 23) & 255) - 127;
      esh = esh < -126 ? -126 : (esh > 126 ? 126 : esh);
      float sc = __int_as_float((127 - esh) << 23);
      A += esh;

      float bj[8];
      bj[0] = ((a0.x+a1.x)+(a2.x+a3.x))*sc;
      bj[1] = ((a0.y+a1.y)+(a2.y+a3.y))*sc;
      bj[2] = ((a0.z+a1.z)+(a2.z+a3.z))*sc;
      bj[3] = ((a0.w+a1.w)+(a2.w+a3.w))*sc;
      bj[4] = ((b0.x+b1.x)+(b2.x+b3.x))*sc;
      bj[5] = ((b0.y+b1.y)+(b2.y+b3.y))*sc;
      bj[6] = ((b0.z+b1.z)+(b2.z+b3.z))*sc;
      bj[7] = ((b0.w+b1.w)+(b2.w+b3.w))*sc;

      // acc_i = sum_k E[i][8w+k] * beta[8w+k] ; E column-major: Ecm[(8w+k)*32 + i]
      const float* ec = &Ecm[eb*1024];
      float acc = 0.f;
      #pragma unroll
      for (int m = 0; m < 8; ++m)
        acc = fmaf(ec[(8*w+m)*VV + j], bj[m], acc);
      part[(pb^1)*128 + w*32 + j] = acc;
    }
    __syncthreads();
    if (w == 0){
      g_beta[b*VV + j] = part[0*128 + 0*32 + j] + part[0*128 + 1*32 + j]
                       + part[0*128 + 2*32 + j] + part[0*128 + 3*32 + j];
      if (j == 0){ g_Ab[b] = (float)A; }
    }
    if (tid == 0) g_numb[b] = num + w_final[tg[LB]];

  } else {
    // ======================= CHUNK matrix products: 6 chunks x 32 steps =======================
    const int idx = bid - 128;
    const int b = idx / NCH, c = idx % NCH;
    const int toff = TOFF + c * LL;
    float* tile = (float*)(pool);                 // NSTG*1024
    float* E_sm = (float*)(pool + 16384);         // 2*1024
    float* P_sm = (float*)(pool + 24576);         // 2*1024
    float* craw = (float*)(pool + 32768);         // 1024
    int*   tg   = (int*)  (pool + 36864);         // LL+1
    const float* sb = scores + ((size_t)b*TT + toff) * (VV*VV);
    const int r0 = w * 8;

    for (int k = tid; k < VV*VV; k += NTHR) craw[k] = w_tx[k] + w_dur[k];
    if (tid <= LL) tg[tid] = ld_tgt(targets_raw, is64, (long long)b*(TT+1) + toff + tid);

    #pragma unroll
    for (int p = 0; p < NSTG-1; ++p){
      cpasync16(&tile[p*1024 + tid*8],     sb + p*VV*VV + tid*8);
      cpasync16(&tile[p*1024 + tid*8 + 4], sb + p*VV*VV + tid*8 + 4);
      asm volatile("cp.async.commit_group;");
    }

    float c2own[8];
    #pragma unroll
    for (int k = 0; k < 8; ++k)
      c2own[k] = (w_tx[tid*8+k] + w_dur[tid*8+k]) * F_LOG2E;

    __syncthreads();

    int A = 0; float num = 0.f;

    for (int t = 0; t < LL; ++t){
      asm volatile("cp.async.wait_group %0;" :: "n"(NSTG-2));
      const int slot = t & (NSTG-1);
      {
        const float* tp = &tile[slot*1024 + tid*8];
        float e0 = ex2f_(fmaf(tp[0], F_LOG2E, c2own[0]));
        float e1 = ex2f_(fmaf(tp[1], F_LOG2E, c2own[1]));
        float e2 = ex2f_(fmaf(tp[2], F_LOG2E, c2own[2]));
        float e3 = ex2f_(fmaf(tp[3], F_LOG2E, c2own[3]));
        float e4 = ex2f_(fmaf(tp[4], F_LOG2E, c2own[4]));
        float e5 = ex2f_(fmaf(tp[5], F_LOG2E, c2own[5]));
        float e6 = ex2f_(fmaf(tp[6], F_LOG2E, c2own[6]));
        float e7 = ex2f_(fmaf(tp[7], F_LOG2E, c2own[7]));
        float* dst = (t == 0) ? &P_sm[0*1024 + tid*8] : &E_sm[(t&1)*1024 + tid*8];
        *(float4*)dst       = make_float4(e0, e1, e2, e3);
        *(float4*)(dst + 4) = make_float4(e4, e5, e6, e7);
      }
      __syncthreads();

      { int tl = t + NSTG - 1;
        if (tl < LL){
          float* d = &tile[(tl & (NSTG-1))*1024];
          const float* g = sb + (size_t)tl*VV*VV;
          cpasync16(d + tid*8, g + tid*8); cpasync16(d + tid*8 + 4, g + tid*8 + 4);
        }
        asm volatile("cp.async.commit_group;");
      }

      if (tid == 0){
        int ix = tg[t]*VV + tg[t+1];
        num += tile[slot*1024 + ix] + craw[ix];
      }

      if (t > 0){
        const int pbR = (t-1) & 1, pbW = t & 1, eb = t & 1;
        float p00 = P_sm[pbR*1024];
        int esh = ((__float_as_int(p00) >> 23) & 255) - 127;
        float sc = __int_as_float((127 - esh) << 23);
        A += esh;

        ull E2[16];
        #pragma unroll
        for (int i2 = 0; i2 < 16; ++i2)
          E2[i2] = pack2_(E_sm[eb*1024 + (2*i2)*VV + j], E_sm[eb*1024 + (2*i2+1)*VV + j]);

        ull acc[8];
        #pragma unroll
        for (int r = 0; r < 8; ++r) acc[r] = 0ull;
        #pragma unroll
        for (int i4 = 0; i4 < 8; ++i4){
          #pragma unroll
          for (int r = 0; r < 8; ++r){
            ulonglong2 q = *(const ulonglong2*)&P_sm[pbR*1024 + (r0+r)*VV + 4*i4];
            acc[r] = fma2_(q.x, E2[2*i4],   acc[r]);
            acc[r] = fma2_(q.y, E2[2*i4+1], acc[r]);
          }
        }
        #pragma unroll
        for (int r = 0; r < 8; ++r){
          float lo, hi; unpack2_(acc[r], lo, hi);
          P_sm[pbW*1024 + (r0+r)*VV + j] = (lo + hi) * sc;
        }
      }
    }
    __syncthreads();
    const float* Pf = &P_sm[((LL-1) & 1)*1024];
    float* gout = &g_P[(size_t)idx * (VV*VV)];
    for (int k = tid; k < VV*VV; k += NTHR) gout[k] = Pf[k];
    if (tid == 0){ g_Ac[idx] = (float)A; g_numc[idx] = num; }
  }
}

// ===================== combine: alpha * P1..P6 * beta =====================
__global__ __launch_bounds__(32)
void crf_combine(float* __restrict__ out)
{
  const int b = blockIdx.x;
  const int j = threadIdx.x;

  float v = g_alpha[b*VV + j];
  float A = g_Af[b] + g_Ab[b];
  float num = g_numf[b] + g_numb[b];

  float nc = (j < NCH) ? g_numc[b*NCH + j] : 0.f;
  float ac = (j < NCH) ? g_Ac[b*NCH + j]  : 0.f;
  #pragma unroll
  for (int off = 16; off; off >>= 1){
    nc += __shfl_xor_sync(0xffffffffu, nc, off);
    ac += __shfl_xor_sync(0xffffffffu, ac, off);
  }
  num += nc; A += ac;

  // prefetch chunk 0
  float p[32];
  { const float* Pc = &g_P[((size_t)b*NCH + 0) * (VV*VV)];
    #pragma unroll
    for (int i = 0; i < 32; ++i) p[i] = Pc[i*VV + j]; }

  for (int c = 0; c < NCH; ++c){
    float pn[32];
    if (c + 1 < NCH){
      const float* Pc = &g_P[((size_t)b*NCH + c + 1) * (VV*VV)];
      #pragma unroll
      for (int i = 0; i < 32; ++i) pn[i] = Pc[i*VV + j];
    }
    float a0 = __shfl_sync(0xffffffffu, v, 0);
    int esh = ((__float_as_int(a0) >> 23) & 255) - 127;
    esh = esh < -126 ? -126 : (esh > 126 ? 126 : esh);
    v *= __int_as_float((127 - esh) << 23);
    A += (float)esh;

    float n0 = 0.f, n1 = 0.f, n2 = 0.f, n3 = 0.f;
    #pragma unroll
    for (int i = 0; i < 32; i += 4){
      n0 = fmaf(__shfl_sync(0xffffffffu, v, i  ), p[i  ], n0);
      n1 = fmaf(__shfl_sync(0xffffffffu, v, i+1), p[i+1], n1);
      n2 = fmaf(__shfl_sync(0xffffffffu, v, i+2), p[i+2], n2);
      n3 = fmaf(__shfl_sync(0xffffffffu, v, i+3), p[i+3], n3);
    }
    v = (n0 + n1) + (n2 + n3);
    if (c + 1 < NCH){
      #pragma unroll
      for (int i = 0; i < 32; ++i) p[i] = pn[i];
    }
  }

  float term = v * g_beta[b*VV + j];
  #pragma unroll
  for (int off = 16; off; off >>= 1)
    term += __shfl_xor_sync(0xffffffffu, term, off);

  if (j == 0)
    out[b] = num - F_LN2 * (lg2f_(term) + A);
}

extern "C" void kernel_launch(void* const* d_in, const int* in_sizes, int n_in,
                              void* d_out, int out_size)
{
  const float* scores  = (const float*)d_in[0];
  const void*  targets = d_in[1];
  const float* w_tx    = (const float*)d_in[2];
  const float* w_init  = (const float*)d_in[3];
  const float* w_final = (const float*)d_in[4];
  const float* w_dur   = (const float*)d_in[5];
  float* out = (float*)d_out;

  // launch pattern (dummy, fused, combine, dummy): global launch index 5 % 4 = 1
  // -> ncu -s 5 -c 1 profiles the fused kernel.
  knop<<<1, 32>>>();
  crf_fused<<<512, NTHR>>>(scores, targets, w_tx, w_init, w_final, w_dur);
  crf_combine<<<B_, 32>>>(out);
  knop<<<1, 32>>>();
}

// round 6
// speedup vs baseline: 1.6009x; 1.6009x over previous
#include <cuda_runtime.h>
#include <cstdint>

#define TT 512
#define HF 256
#define VV 32
#define RD 8
#define NTHR 128
#define F_LOG2E 1.4426950408889634f
#define F_LN2   0.6931471805599453f

typedef unsigned long long ull;

__device__ float g_alpha[64*VV];
__device__ float g_beta [64*VV];
__device__ float g_Asum[128];
__device__ float g_nums[128];

__device__ __forceinline__ float ex2f_(float x){ float y; asm("ex2.approx.ftz.f32 %0, %1;" : "=f"(y) : "f"(x)); return y; }
__device__ __forceinline__ float lg2f_(float x){ float y; asm("lg2.approx.ftz.f32 %0, %1;" : "=f"(y) : "f"(x)); return y; }
__device__ __forceinline__ ull add2_(ull a, ull b){ ull r; asm("add.rn.f32x2 %0, %1, %2;" : "=l"(r) : "l"(a), "l"(b)); return r; }
__device__ __forceinline__ ull mul2_(ull a, ull b){ ull r; asm("mul.rn.f32x2 %0, %1, %2;" : "=l"(r) : "l"(a), "l"(b)); return r; }
__device__ __forceinline__ ull fma2_(ull a, ull b, ull c){ ull r; asm("fma.rn.f32x2 %0, %1, %2, %3;" : "=l"(r) : "l"(a), "l"(b), "l"(c)); return r; }
__device__ __forceinline__ ull pack2_(float lo, float hi){ ull r; asm("mov.b64 %0, {%1, %2};" : "=l"(r) : "f"(lo), "f"(hi)); return r; }
__device__ __forceinline__ void unpack2_(ull v, float& lo, float& hi){ asm("mov.b64 {%0, %1}, %2;" : "=f"(lo), "=f"(hi) : "l"(v)); }
__device__ __forceinline__ int tgt_is64(const int* t32){
  int is64 = 1;
  #pragma unroll
  for (int k = 1; k < 64; k += 2) if (t32[k] != 0) is64 = 0;
  return is64;
}
__device__ __forceinline__ int ld_tgt(const void* traw, int is64, long long idx){
  return is64 ? (int)((const long long*)traw)[idx] : ((const int*)traw)[idx];
}

// core step: reduce partials over 4 warps (pairs blk..blk+7), dot with e, renorm, store
#define CORE_STEP(T)                                                              \
  {                                                                               \
    const int pb = (T) & 1;                                                       \
    const float* pp = &part[pb][0][0];                                            \
    ulonglong2 p0 = *(const ulonglong2*)(pp + 0*VV + blk);                        \
    ulonglong2 p1 = *(const ulonglong2*)(pp + 1*VV + blk);                        \
    ulonglong2 p2 = *(const ulonglong2*)(pp + 2*VV + blk);                        \
    ulonglong2 p3 = *(const ulonglong2*)(pp + 3*VV + blk);                        \
    ulonglong2 q0 = *(const ulonglong2*)(pp + 0*VV + blk + 4);                    \
    ulonglong2 q1 = *(const ulonglong2*)(pp + 1*VV + blk + 4);                    \
    ulonglong2 q2 = *(const ulonglong2*)(pp + 2*VV + blk + 4);                    \
    ulonglong2 q3 = *(const ulonglong2*)(pp + 3*VV + blk + 4);                    \
    ull uA = add2_(add2_(p0.x, p1.x), add2_(p2.x, p3.x));                         \
    ull uB = add2_(add2_(p0.y, p1.y), add2_(p2.y, p3.y));                         \
    ull uC = add2_(add2_(q0.x, q1.x), add2_(q2.x, q3.x));                         \
    ull uD = add2_(add2_(q0.y, q1.y), add2_(q2.y, q3.y));                         \
    float ut0 = (pp[0] + pp[VV]) + (pp[2*VV] + pp[3*VV]);                         \
    int esh = ((__float_as_int(ut0) >> 23) & 255) - 127;                          \
    esh = esh < -126 ? -126 : (esh > 126 ? 126 : esh);                            \
    float sc = __int_as_float((127 - esh) << 23);                                 \
    A += esh;                                                                     \
    ull e01 = pack2_(e0, e1), e23 = pack2_(e2, e3);                               \
    ull e45 = pack2_(e4, e5), e67 = pack2_(e6, e7);                               \
    ull m0 = fma2_(e23, uB, mul2_(e01, uA));                                      \
    ull m1 = fma2_(e67, uD, mul2_(e45, uC));                                      \
    float lo, hi; unpack2_(add2_(m0, m1), lo, hi);                                \
    part[pb ^ 1][w][lane] = (lo + hi) * sc;                                       \
  }

__global__ __launch_bounds__(NTHR, 1)
void crf_scan(const float* __restrict__ scores,
              const void*  __restrict__ targets_raw,
              const float* __restrict__ w_tx,
              const float* __restrict__ w_init,
              const float* __restrict__ w_final,
              const float* __restrict__ w_dur)
{
  __shared__ __align__(16) float part[2][4][VV];
  __shared__ float craw[VV*VV];
  __shared__ int   tg[HF+1];

  const int bid  = blockIdx.x;
  const int fwd  = (bid < 64);
  const int b    = fwd ? bid : (bid - 64);
  const int tid  = threadIdx.x;
  const int lane = tid & 31;
  const int w    = tid >> 5;
  const int blk  = w * 8;                 // fwd: row block; bwd: col block
  const int is64 = tgt_is64((const int*)targets_raw);
  const float* sb = scores + (size_t)b * TT * (VV*VV);

  for (int k = tid; k < VV*VV; k += NTHR) craw[k] = w_tx[k] + w_dur[k];
  { const long long tb = (long long)b*(TT+1) + (fwd ? 0 : HF);
    for (int k = tid; k <= HF; k += NTHR) tg[k] = ld_tgt(targets_raw, is64, tb + k); }

  part[0][w][lane] = (w == 0) ? ex2f_((fwd ? w_init[lane] : w_final[lane]) * F_LOG2E) : 0.f;

  float c2[8];
  #pragma unroll
  for (int d = 0; d < 8; ++d){
    int cell = fwd ? ((blk + d)*VV + lane) : (lane*VV + blk + d);
    c2[d] = (w_tx[cell] + w_dur[cell]) * F_LOG2E;
  }

  __syncthreads();

  const bool isnum = (tid == 32);
  int A = 0; float num = 0.f;

  if (fwd){
    // thread cells: (blk+d, lane) of tile t -> sb + t*1024 + (blk+d)*32 + lane
    const float* p0 = sb + blk*VV + lane;
    float raw[RD][8];
    #pragma unroll
    for (int p = 0; p < RD; ++p){
      #pragma unroll
      for (int d = 0; d < 8; ++d) raw[p][d] = p0[p*1024 + d*VV];
    }
    float nring[RD];
    if (isnum){
      #pragma unroll
      for (int p = 0; p < RD; ++p) nring[p] = sb[p*1024 + tg[p]*VV + tg[p+1]];
    }

    #pragma unroll 8
    for (int t = 0; t < HF; ++t){
      const int sl = t & (RD-1);
      float e0 = ex2f_(fmaf(raw[sl][0], F_LOG2E, c2[0]));
      float e1 = ex2f_(fmaf(raw[sl][1], F_LOG2E, c2[1]));
      float e2 = ex2f_(fmaf(raw[sl][2], F_LOG2E, c2[2]));
      float e3 = ex2f_(fmaf(raw[sl][3], F_LOG2E, c2[3]));
      float e4 = ex2f_(fmaf(raw[sl][4], F_LOG2E, c2[4]));
      float e5 = ex2f_(fmaf(raw[sl][5], F_LOG2E, c2[5]));
      float e6 = ex2f_(fmaf(raw[sl][6], F_LOG2E, c2[6]));
      float e7 = ex2f_(fmaf(raw[sl][7], F_LOG2E, c2[7]));
      float nv = 0.f; int nix = 0;
      if (isnum){ nix = tg[t]*VV + tg[t+1]; nv = nring[sl]; }
      if (t + RD < HF){
        const float* pr = p0 + (t+RD)*1024;
        #pragma unroll
        for (int d = 0; d < 8; ++d) raw[sl][d] = pr[d*VV];
        if (isnum) nring[sl] = sb[(t+RD)*1024 + tg[t+RD]*VV + tg[t+RD+1]];
      }
      __syncthreads();
      CORE_STEP(t)
      if (isnum) num += nv + craw[nix];
    }
  } else {
    // bwd: step k processes tile t=511-k; thread cells: (lane, blk+d) -> contiguous
    const float* q0 = sb + (size_t)(TT-1)*1024 + lane*VV + blk;
    float4 raw[RD][2];
    #pragma unroll
    for (int p = 0; p < RD; ++p){
      raw[p][0] = *(const float4*)(q0 - p*1024);
      raw[p][1] = *(const float4*)(q0 - p*1024 + 4);
    }
    float nring[RD];
    if (isnum){
      #pragma unroll
      for (int p = 0; p < RD; ++p)
        nring[p] = sb[(size_t)(TT-1-p)*1024 + tg[HF-1-p]*VV + tg[HF-p]];
    }

    #pragma unroll 8
    for (int t = 0; t < HF; ++t){
      const int sl = t & (RD-1);
      float e0 = ex2f_(fmaf(raw[sl][0].x, F_LOG2E, c2[0]));
      float e1 = ex2f_(fmaf(raw[sl][0].y, F_LOG2E, c2[1]));
      float e2 = ex2f_(fmaf(raw[sl][0].z, F_LOG2E, c2[2]));
      float e3 = ex2f_(fmaf(raw[sl][0].w, F_LOG2E, c2[3]));
      float e4 = ex2f_(fmaf(raw[sl][1].x, F_LOG2E, c2[4]));
      float e5 = ex2f_(fmaf(raw[sl][1].y, F_LOG2E, c2[5]));
      float e6 = ex2f_(fmaf(raw[sl][1].z, F_LOG2E, c2[6]));
      float e7 = ex2f_(fmaf(raw[sl][1].w, F_LOG2E, c2[7]));
      float nv = 0.f; int nix = 0;
      if (isnum){ nix = tg[HF-1-t]*VV + tg[HF-t]; nv = nring[sl]; }
      if (t + RD < HF){
        const float* pr = q0 - (size_t)(t+RD)*1024;
        raw[sl][0] = *(const float4*)(pr);
        raw[sl][1] = *(const float4*)(pr + 4);
        if (isnum)
          nring[sl] = sb[(size_t)(TT-1-(t+RD))*1024 + tg[HF-1-(t+RD)]*VV + tg[HF-(t+RD)]];
      }
      __syncthreads();
      CORE_STEP(t)
      if (isnum) num += nv + craw[nix];
    }
  }

  __syncthreads();
  if (w == 0){
    float v = part[0][0][lane] + part[0][1][lane] + part[0][2][lane] + part[0][3][lane];
    if (fwd) g_alpha[b*VV + lane] = v; else g_beta[b*VV + lane] = v;
    if (lane == 0) g_Asum[bid] = (float)A;
  }
  if (isnum) g_nums[bid] = num + (fwd ? w_init[tg[0]] : w_final[tg[HF]]);
}

__global__ __launch_bounds__(32)
void crf_combine(float* __restrict__ out)
{
  const int b = blockIdx.x;
  const int j = threadIdx.x;
  float term = g_alpha[b*VV + j] * g_beta[b*VV + j];
  #pragma unroll
  for (int off = 16; off; off >>= 1)
    term += __shfl_xor_sync(0xffffffffu, term, off);
  if (j == 0)
    out[b] = (g_nums[b] + g_nums[64 + b])
           - F_LN2 * (lg2f_(term) + g_Asum[b] + g_Asum[64 + b]);
}

extern "C" void kernel_launch(void* const* d_in, const int* in_sizes, int n_in,
                              void* d_out, int out_size)
{
  const float* scores  = (const float*)d_in[0];
  const void*  targets = d_in[1];
  const float* w_tx    = (const float*)d_in[2];
  const float* w_init  = (const float*)d_in[3];
  const float* w_final = (const float*)d_in[4];
  const float* w_dur   = (const float*)d_in[5];
  float* out = (float*)d_out;

  crf_scan<<<128, NTHR>>>(scores, targets, w_tx, w_init, w_final, w_dur);
  crf_combine<<<64, 32>>>(out);
}

// round 7
// speedup vs baseline: 1.8530x; 1.1574x over previous
#include <cuda_runtime.h>
#include <cstdint>

#define TT 512
#define HF 256
#define VV 32
#define RD 4
#define F_LOG2E 1.4426950408889634f
#define F_LN2   0.6931471805599453f

__device__ __forceinline__ float ex2f_(float x){ float y; asm("ex2.approx.ftz.f32 %0, %1;" : "=f"(y) : "f"(x)); return y; }
__device__ __forceinline__ float lg2f_(float x){ float y; asm("lg2.approx.ftz.f32 %0, %1;" : "=f"(y) : "f"(x)); return y; }
__device__ __forceinline__ void cpa16(uint32_t s, const void* g){
  asm volatile("cp.async.cg.shared.global [%0], [%1], 16;" :: "r"(s), "l"(g));
}
#define CPCOMMIT() asm volatile("cp.async.commit_group;")
#define CPWAIT3()  asm volatile("cp.async.wait_group 3;")

__device__ __forceinline__ int tgt_is64(const int* t32){
  int is64 = 1;
  #pragma unroll
  for (int k = 1; k < 64; k += 2) if (t32[k] != 0) is64 = 0;
  return is64;
}
__device__ __forceinline__ int ld_tgt(const void* traw, int is64, long long idx){
  return is64 ? (int)((const long long*)traw)[idx] : ((const int*)traw)[idx];
}

__global__ __launch_bounds__(64, 1)
void crf_kernel(const float* __restrict__ scores,
                const void*  __restrict__ traw,
                const float* __restrict__ w_tx,
                const float* __restrict__ w_init,
                const float* __restrict__ w_final,
                const float* __restrict__ w_dur,
                float* __restrict__ out)
{
  __shared__ __align__(16) float ring[2][RD*1024];   // per-warp cp.async ring, 16KB each
  __shared__ float exch[2][VV];
  __shared__ float numsm[64];
  __shared__ int   Ash[2];

  const int b    = blockIdx.x;
  const int tid  = threadIdx.x;
  const int lane = tid & 31;
  const int wid  = tid >> 5;
  const float* sb = scores + (size_t)b * TT * 1024;

  const uint32_t rbase = (uint32_t)__cvta_generic_to_shared(&ring[wid][0]);

  // cp.async destination offsets for this lane's 8 chunks (16B-XOR swizzle):
  // chunk g = i*32+lane maps to (row=g>>3, c4=g&7) stored at position c4^(row&7).
  uint32_t dsto[8];
  #pragma unroll
  for (int i = 0; i < 8; ++i){
    int g = i*32 + lane, row = g >> 3, c4 = g & 7;
    dsto[i] = (uint32_t)(row*128 + ((c4 ^ (row & 7)) * 16));
  }

  // per-lane constants: fwd lane j needs column j of (w_tx+w_dur); bwd lane i needs row i
  float c2[VV];
  float u;
  if (wid == 0){
    #pragma unroll
    for (int i = 0; i < VV; ++i) c2[i] = (w_tx[i*VV + lane] + w_dur[i*VV + lane]) * F_LOG2E;
    u = ex2f_(w_init[lane] * F_LOG2E);
  } else {
    #pragma unroll
    for (int i = 0; i < VV; ++i) c2[i] = (w_tx[lane*VV + i] + w_dur[lane*VV + i]) * F_LOG2E;
    u = ex2f_(w_final[lane] * F_LOG2E);
  }

  int A = 0;

  if (wid == 0){
    // ---------------- FORWARD: alpha_{t+1}[j] = sum_i e_t[i][j] * alpha_t[i], t = 0..255
    #pragma unroll
    for (int p = 0; p < RD-1; ++p){
      const char* g = (const char*)(sb + (size_t)p*1024);
      #pragma unroll
      for (int i = 0; i < 8; ++i) cpa16(rbase + (uint32_t)p*4096u + dsto[i], g + i*512 + lane*16);
      CPCOMMIT();
    }
    // column-read offsets: word (lane) of row i sits at i*128 + ((lane>>2)^(i&7))*16 + (lane&3)*4
    uint32_t off8[8];
    #pragma unroll
    for (int k = 0; k < 8; ++k) off8[k] = (uint32_t)((((lane>>2) ^ k) * 16) + (lane & 3) * 4);

    for (int tb = 0; tb < HF; tb += RD){
      #pragma unroll
      for (int q = 0; q < RD; ++q){
        const int t = tb + q;
        { // prefetch tile t+3 into slot (t+3)&3 (freed at step t-1)
          const int tl = t + RD - 1;
          if (tl < HF){
            const char* g = (const char*)(sb + (size_t)tl*1024);
            const uint32_t d = rbase + (uint32_t)(tl & (RD-1)) * 4096u;
            #pragma unroll
            for (int i = 0; i < 8; ++i) cpa16(d + dsto[i], g + i*512 + lane*16);
          }
          CPCOMMIT();
        }
        CPWAIT3();            // tile t resident
        __syncwarp();
        const char* tp = (const char*)&ring[0][0] + (t & (RD-1))*4096;
        float a0=0.f, a1=0.f, a2=0.f, a3=0.f;
        #pragma unroll
        for (int i = 0; i < VV; i += 4){
          float s0 = *(const float*)(tp + (i  )*128 + off8[(i  ) & 7]);
          float s1 = *(const float*)(tp + (i+1)*128 + off8[(i+1) & 7]);
          float s2 = *(const float*)(tp + (i+2)*128 + off8[(i+2) & 7]);
          float s3 = *(const float*)(tp + (i+3)*128 + off8[(i+3) & 7]);
          float u0 = __shfl_sync(0xffffffffu, u, i  );
          float u1 = __shfl_sync(0xffffffffu, u, i+1);
          float u2 = __shfl_sync(0xffffffffu, u, i+2);
          float u3 = __shfl_sync(0xffffffffu, u, i+3);
          a0 = fmaf(ex2f_(fmaf(s0, F_LOG2E, c2[i  ])), u0, a0);
          a1 = fmaf(ex2f_(fmaf(s1, F_LOG2E, c2[i+1])), u1, a1);
          a2 = fmaf(ex2f_(fmaf(s2, F_LOG2E, c2[i+2])), u2, a2);
          a3 = fmaf(ex2f_(fmaf(s3, F_LOG2E, c2[i+3])), u3, a3);
        }
        u = (a0 + a1) + (a2 + a3);
      }
      // renorm every 4 steps: exact power-of-2 by warp-max exponent
      float m = u;
      #pragma unroll
      for (int o = 16; o; o >>= 1) m = fmaxf(m, __shfl_xor_sync(0xffffffffu, m, o));
      int esh = ((__float_as_int(m) >> 23) & 255) - 127;
      esh = esh < -126 ? -126 : (esh > 126 ? 126 : esh);
      u *= __int_as_float((127 - esh) << 23);
      A += esh;
    }
  } else {
    // ---------------- BACKWARD: beta_t[i] = sum_j e_t[i][j] * beta_{t+1}[j], t = 511..256
    #pragma unroll
    for (int p = 0; p < RD-1; ++p){
      const char* g = (const char*)(sb + (size_t)(TT-1-p)*1024);
      #pragma unroll
      for (int i = 0; i < 8; ++i) cpa16(rbase + (uint32_t)p*4096u + dsto[i], g + i*512 + lane*16);
      CPCOMMIT();
    }
    // row-read offsets: original chunk c4 of row lane sits at position c4^(lane&7)
    uint32_t roff[8];
    #pragma unroll
    for (int k = 0; k < 8; ++k) roff[k] = (uint32_t)((k ^ (lane & 7)) * 16);

    for (int tb = 0; tb < HF; tb += RD){
      #pragma unroll
      for (int q = 0; q < RD; ++q){
        const int t = tb + q;
        {
          const int tl = t + RD - 1;
          if (tl < HF){
            const char* g = (const char*)(sb + (size_t)(TT-1-tl)*1024);
            const uint32_t d = rbase + (uint32_t)(tl & (RD-1)) * 4096u;
            #pragma unroll
            for (int i = 0; i < 8; ++i) cpa16(d + dsto[i], g + i*512 + lane*16);
          }
          CPCOMMIT();
        }
        CPWAIT3();
        __syncwarp();
        const char* tp = (const char*)&ring[1][0] + (t & (RD-1))*4096 + lane*128;
        float a0=0.f, a1=0.f, a2=0.f, a3=0.f;
        #pragma unroll
        for (int c4 = 0; c4 < 8; ++c4){
          float4 v = *(const float4*)(tp + roff[c4]);
          const int j = c4*4;
          float u0 = __shfl_sync(0xffffffffu, u, j  );
          float u1 = __shfl_sync(0xffffffffu, u, j+1);
          float u2 = __shfl_sync(0xffffffffu, u, j+2);
          float u3 = __shfl_sync(0xffffffffu, u, j+3);
          a0 = fmaf(ex2f_(fmaf(v.x, F_LOG2E, c2[j  ])), u0, a0);
          a1 = fmaf(ex2f_(fmaf(v.y, F_LOG2E, c2[j+1])), u1, a1);
          a2 = fmaf(ex2f_(fmaf(v.z, F_LOG2E, c2[j+2])), u2, a2);
          a3 = fmaf(ex2f_(fmaf(v.w, F_LOG2E, c2[j+3])), u3, a3);
        }
        u = (a0 + a1) + (a2 + a3);
      }
      float m = u;
      #pragma unroll
      for (int o = 16; o; o >>= 1) m = fmaxf(m, __shfl_xor_sync(0xffffffffu, m, o));
      int esh = ((__float_as_int(m) >> 23) & 255) - 127;
      esh = esh < -126 ? -126 : (esh > 126 ? 126 : esh);
      u *= __int_as_float((127 - esh) << 23);
      A += esh;
    }
  }

  exch[wid][lane] = u;
  if (lane == 0) Ash[wid] = A;

  // ---------------- numerator: thread tid gathers steps [tid*8, tid*8+8)
  const int is64 = tgt_is64((const int*)traw);
  const long long tbase = (long long)b * (TT+1);
  float np = 0.f;
  int tga = ld_tgt(traw, is64, tbase + tid*8);
  #pragma unroll
  for (int k = 0; k < 8; ++k){
    int tgb = ld_tgt(traw, is64, tbase + tid*8 + k + 1);
    int ix = tga*VV + tgb;
    np += sb[(size_t)(tid*8 + k)*1024 + ix] + w_tx[ix] + w_dur[ix];
    tga = tgb;
  }
  numsm[tid] = np;
  __syncthreads();

  if (wid == 0){
    float term = exch[0][lane] * exch[1][lane];   // Z = sum_j alpha_256[j] * beta_256[j]
    float ns   = numsm[lane] + numsm[32 + lane];
    #pragma unroll
    for (int o = 16; o; o >>= 1){
      term += __shfl_xor_sync(0xffffffffu, term, o);
      ns   += __shfl_xor_sync(0xffffffffu, ns,   o);
    }
    if (lane == 0){
      int t0 = ld_tgt(traw, is64, tbase);
      int tT = ld_tgt(traw, is64, tbase + TT);
      float num = ns + w_init[t0] + w_final[tT];
      out[b] = num - F_LN2 * (lg2f_(term) + (float)(Ash[0] + Ash[1]));
    }
  }
}

extern "C" void kernel_launch(void* const* d_in, const int* in_sizes, int n_in,
                              void* d_out, int out_size)
{
  const float* scores  = (const float*)d_in[0];
  const void*  targets = d_in[1];
  const float* w_tx    = (const float*)d_in[2];
  const float* w_init  = (const float*)d_in[3];
  const float* w_final = (const float*)d_in[4];
  const float* w_dur   = (const float*)d_in[5];
  float* out = (float*)d_out;

  crf_kernel<<<64, 64>>>(scores, targets, w_tx, w_init, w_final, w_dur, out);
}